// round 1
// baseline (speedup 1.0000x reference)
#include <cuda_runtime.h>
#include <cuda_bf16.h>

#define NROWS 4000000

__global__ __launch_bounds__(256) void rinter_area_kernel(
    const float4* __restrict__ pts,      // N rows * 4 float4 each (16 floats)
    const int* __restrict__ num_of_inter,
    float* __restrict__ out,
    int n)
{
    int i = blockIdx.x * blockDim.x + threadIdx.x;
    if (i >= n) return;

    // Load 16 floats = 4 float4, contiguous per row.
    const float4* row = pts + (size_t)i * 4;
    float4 a = row[0];
    float4 b = row[1];
    float4 c = row[2];
    float4 d = row[3];

    // points: p[k] = (x,y), k=0..7
    float px[8], py[8];
    px[0] = a.x; py[0] = a.y; px[1] = a.z; py[1] = a.w;
    px[2] = b.x; py[2] = b.y; px[3] = b.z; py[3] = b.w;
    px[4] = c.x; py[4] = c.y; px[5] = c.z; py[5] = c.w;
    px[6] = d.x; py[6] = d.y; px[7] = d.z; py[7] = d.w;

    int ntri = num_of_inter[i] - 2;  // triangles 0..5 valid if idx < ntri

    float p1x = px[0], p1y = py[0];
    float sum = 0.0f;
    #pragma unroll
    for (int t = 0; t < 6; t++) {
        float p2x = px[1 + t], p2y = py[1 + t];
        float p3x = px[2 + t], p3y = py[2 + t];
        float cross = (p1x - p3x) * (p2y - p3y) - (p1y - p3y) * (p2x - p3x);
        float area = fabsf(cross) * 0.5f;
        sum += (t < ntri) ? area : 0.0f;
    }
    out[i] = sum;
}

extern "C" void kernel_launch(void* const* d_in, const int* in_sizes, int n_in,
                              void* d_out, int out_size) {
    const float4* pts = (const float4*)d_in[0];
    const int* num_of_inter = (const int*)d_in[1];
    float* out = (float*)d_out;
    int n = in_sizes[1];  // N rows (int input has N elements)

    int threads = 256;
    int blocks = (n + threads - 1) / threads;
    rinter_area_kernel<<<blocks, threads>>>(pts, num_of_inter, out, n);
}